// round 9
// baseline (speedup 1.0000x reference)
#include <cuda_runtime.h>
#include <cstdint>

#define DIM 512
#define NSTEP 50

typedef unsigned long long u64;

__device__ float g_loss_accum;
__device__ float2 g_ae[NSTEP + 1];   // per-step {A_t, E_t}

__device__ __forceinline__ float rsqrt_approx(float x) {
    float y; asm("rsqrt.approx.f32 %0, %1;" : "=f"(y) : "f"(x)); return y;
}
__device__ __forceinline__ float sqrt_approx(float x) {
    float y; asm("sqrt.approx.f32 %0, %1;" : "=f"(y) : "f"(x)); return y;
}
__device__ __forceinline__ u64 pk2(float lo, float hi) {
    u64 r; asm("mov.b64 %0, {%1,%2};" : "=l"(r) : "f"(lo), "f"(hi)); return r;
}
__device__ __forceinline__ void unpk2(float& lo, float& hi, u64 v) {
    asm("mov.b64 {%0,%1}, %2;" : "=f"(lo), "=f"(hi) : "l"(v));
}
__device__ __forceinline__ u64 pk2i(unsigned lo, unsigned hi) {
    u64 r; asm("mov.b64 %0, {%1,%2};" : "=l"(r) : "r"(lo), "r"(hi)); return r;
}
#define FMA2(d, a, b, c) asm("fma.rn.f32x2 %0, %1, %2, %3;" : "=l"(d) : "l"(a), "l"(b), "l"(c))
#define MUL2(d, a, b)    asm("mul.rn.f32x2 %0, %1, %2;"     : "=l"(d) : "l"(a), "l"(b))
#define ADD2(d, a, b)    asm("add.rn.f32x2 %0, %1, %2;"     : "=l"(d) : "l"(a), "l"(b))

// Init: zero loss accumulator; precompute per-step Adam scalars (fp64),
// one thread per step.
//   rescaled Adam: m' = m/(C1*S), v' = v/(C2*S^2), S = 1/B
//   ds = sqrt(C2/(1-B2^t)); A_t = LR*C1/((1-B1^t)*ds); E_t = (EPS/S)/ds
__global__ void wm_init_kernel() {
    const int t = threadIdx.x;
    if (t == 0) g_loss_accum = 0.0f;
    if (t >= 1 && t <= NSTEP) {
        double b1t = pow(0.9, (double)t);
        double b2t = pow(0.999, (double)t);
        double ds = sqrt(0.001 / (1.0 - b2t));
        double A  = 0.01 * 0.1 / ((1.0 - b1t) * ds);
        double E  = (1e-8 * 131072.0) / ds;
        g_ae[t] = make_float2((float)A, (float)E);
    }
}

__global__ __launch_bounds__(128, 6) void wm_kernel(
    const float* __restrict__ mu_in,
    const float* __restrict__ logvar_in,
    const float* __restrict__ carrier,
    float* __restrict__ mu_out,
    float* __restrict__ logvar_out,
    int nrows)
{
    // Negated carrier in shared memory: identical for every row.
    __shared__ float4 s_cN[DIM / 4];   // 2 KB
    __shared__ float blk_loss;

    {
        const float4 cv = ((const float4*)carrier)[threadIdx.x];
        s_cN[threadIdx.x] = make_float4(-cv.x, -cv.y, -cv.z, -cv.w);
        if (threadIdx.x == 0) blk_loss = 0.0f;
    }
    __syncthreads();

    const int warp = (blockIdx.x * blockDim.x + threadIdx.x) >> 5;
    const int lane = threadIdx.x & 31;

    const float B1 = 0.9f;
    const float B2 = 0.999f;

    // Packed per-lane state: 8 f32x2 pairs each = 16 floats/lane = 512/warp
    u64 mu2[8], m2[8], v2[8];

    if (warp < nrows) {
        const float4* mrow = (const float4*)(mu_in + (size_t)warp * DIM);
        const float4* lrow = (const float4*)(logvar_in + (size_t)warp * DIM);
        float4*       lout = (float4*)(logvar_out + (size_t)warp * DIM);

#pragma unroll
        for (int i = 0; i < 4; i++) {
            float4 a = mrow[lane + 32 * i];
            mu2[2 * i]     = pk2(a.x, a.y);
            mu2[2 * i + 1] = pk2(a.z, a.w);
            lout[lane + 32 * i] = lrow[lane + 32 * i];  // log_var passthrough
            m2[2 * i] = 0ull; m2[2 * i + 1] = 0ull;
            v2[2 * i] = 0ull; v2[2 * i + 1] = 0ull;
        }

        const u64 B1_2 = pk2(B1, B1);
        const u64 B2_2 = pk2(B2, B2);
        const u64 ONE2 = pk2(1.0f, 1.0f);
        const u64 NEG1_2 = pk2(-1.0f, -1.0f);

        float loss_val = 0.0f;

        // Initial dot/norm partial accumulation (later steps fuse this into
        // the update loop so each step opens directly with the reduction).
        u64 dpa = 0ull, npa = 0ull;
#pragma unroll
        for (int i = 0; i < 4; i++) {
            float4 c4 = s_cN[lane + 32 * i];
            u64 ca = pk2(c4.x, c4.y), cb = pk2(c4.z, c4.w);
            FMA2(dpa, mu2[2 * i],     ca, dpa);
            FMA2(dpa, mu2[2 * i + 1], cb, dpa);
            FMA2(npa, mu2[2 * i],     mu2[2 * i],     npa);
            FMA2(npa, mu2[2 * i + 1], mu2[2 * i + 1], npa);
        }

#pragma unroll 1
        for (int t = 1; t <= NSTEP; ++t) {
            const float2 ae = g_ae[t];
            const float A = ae.x, E = ae.y;

            // Horizontal combine as ONE packed add: {dl,nl} + {dh,nh},
            // then packed butterfly on the {dpn, np} pair.
            float dl, dh, nl, nh;
            unpk2(dl, dh, dpa);
            unpk2(nl, nh, npa);
            u64 red = pk2(dl, nl);
            u64 redh = pk2(dh, nh);
            ADD2(red, red, redh);
#pragma unroll
            for (int off = 16; off; off >>= 1) {
                unsigned rlo = (unsigned)red, rhi = (unsigned)(red >> 32);
                unsigned slo = __shfl_xor_sync(0xffffffffu, rlo, off);
                unsigned shi = __shfl_xor_sync(0xffffffffu, rhi, off);
                u64 other = pk2i(slo, shi);
                ADD2(red, red, other);
            }
            float dpn, np;
            unpk2(dpn, np, red);    // dpn = -(mu.c), np = ||mu||^2

            const float rnorm = rsqrt_approx(np);        // 1/||mu||
            const float norm  = np * rnorm;              // ||mu||
            // COS_THETA == 1.0f in fp32; margin = norm - dot = norm + dpn.
            const float margin = norm + dpn;
            if (t == NSTEP) loss_val = fmaxf(margin, 0.0f);
            // Warp-uniform hinge mask: G *= (margin > 0). Single loop, no
            // duplicated branch body (I$ + scheduling win); AND on ALU pipe.
            const u64 gmask = (margin > 0.0f) ? ~0ull : 0ull;

            const u64 rn2  = pk2(rnorm, rnorm);
            const u64 nA2  = pk2(-A, -A);
            const u64 nEE2 = pk2(-E, -E);

            dpa = 0ull; npa = 0ull;

#pragma unroll
            for (int i = 0; i < 4; i++) {
                float4 c4 = s_cN[lane + 32 * i];
                u64 cN[2] = { pk2(c4.x, c4.y), pk2(c4.z, c4.w) };
#pragma unroll
                for (int q = 0; q < 2; q++) {
                    const int p = 2 * i + q;
                    u64 G;
                    FMA2(G, rn2, mu2[p], cN[q]);         // G = mu/||mu|| - c
                    G &= gmask;                           // hinge mask (ALU)
                    FMA2(m2[p], B1_2, m2[p], G);          // m' = B1*m' + G
                    u64 gg; MUL2(gg, G, G);
                    FMA2(v2[p], B2_2, v2[p], gg);         // v' = B2*v' + G^2
                    float vlo, vhi; unpk2(vlo, vhi, v2[p]);
                    u64 s2 = pk2(sqrt_approx(vlo), sqrt_approx(vhi));
                    // nd = -(s+E) in one packed FMA2; magic seed for 1/d
                    // from bits(nd): 0x7EF477D5-bits(d) == 0xFEF477D5-bits(nd)
                    u64 nd; FMA2(nd, s2, NEG1_2, nEE2);
                    float ndlo, ndhi; unpk2(ndlo, ndhi, nd);
                    u64 y = pk2i(0xFEF477D5u - __float_as_uint(ndlo),
                                 0xFEF477D5u - __float_as_uint(ndhi));
                    // HALLEY (cubic): rel-err -e^3 in ±4e-5, sign-oscillating
                    // (no coherent bias — the R3 1-Newton failure mode).
                    //   w = -A*y0*(1 + e + e^2) = -A/(s+E)*(1 + O(e^3))
                    u64 e;  FMA2(e, nd, y, ONE2);         // e = 1 - d*y0
                    u64 e2; FMA2(e2, e, e, e);            // e + e^2
                    u64 w;  MUL2(w, nA2, y);              // -A*y0
                    FMA2(w, w, e2, w);                    // w *= (1+e+e^2)
                    FMA2(mu2[p], w, m2[p], mu2[p]);       // mu += w*m
                    // fused accumulation for next step's reduction
                    FMA2(dpa, mu2[p], cN[q], dpa);
                    FMA2(npa, mu2[p], mu2[p], npa);
                }
            }
        }

        float4* orow = (float4*)(mu_out + (size_t)warp * DIM);
#pragma unroll
        for (int i = 0; i < 4; i++) {
            float4 a;
            unpk2(a.x, a.y, mu2[2 * i]);
            unpk2(a.z, a.w, mu2[2 * i + 1]);
            orow[lane + 32 * i] = a;
        }

        if (lane == 0) atomicAdd(&blk_loss, loss_val);
    }

    __syncthreads();
    if (threadIdx.x == 0) atomicAdd(&g_loss_accum, blk_loss);
}

__global__ void wm_finalize_kernel(float* __restrict__ out_loss) {
    out_loss[0] = g_loss_accum * (1.0f / 131072.0f);
}

extern "C" void kernel_launch(void* const* d_in, const int* in_sizes, int n_in,
                              void* d_out, int out_size) {
    const float* mu      = (const float*)d_in[0];
    const float* log_var = (const float*)d_in[1];
    const float* carrier = (const float*)d_in[2];

    const int n_elem = in_sizes[0];          // 131072 * 512
    const int nrows  = n_elem / DIM;

    float* out        = (float*)d_out;
    float* mu_out     = out;
    float* logvar_out = out + n_elem;
    float* loss_out   = out + 2 * (size_t)n_elem;

    wm_init_kernel<<<1, 64>>>();

    const int threads = 128;                 // 4 warps (rows) per block
    const int blocks  = (nrows * 32 + threads - 1) / threads;
    wm_kernel<<<blocks, threads>>>(mu, log_var, carrier, mu_out, logvar_out, nrows);

    wm_finalize_kernel<<<1, 1>>>(loss_out);
}

// round 10
// speedup vs baseline: 1.0351x; 1.0351x over previous
#include <cuda_runtime.h>
#include <cstdint>

#define DIM 512
#define NSTEP 50

typedef unsigned long long u64;

__device__ float g_loss_accum;
__device__ float2 g_ae[NSTEP + 1];   // per-step {A_t, E_t}

__device__ __forceinline__ float rsqrt_approx(float x) {
    float y; asm("rsqrt.approx.f32 %0, %1;" : "=f"(y) : "f"(x)); return y;
}
__device__ __forceinline__ float sqrt_approx(float x) {
    float y; asm("sqrt.approx.f32 %0, %1;" : "=f"(y) : "f"(x)); return y;
}
__device__ __forceinline__ u64 pk2(float lo, float hi) {
    u64 r; asm("mov.b64 %0, {%1,%2};" : "=l"(r) : "f"(lo), "f"(hi)); return r;
}
__device__ __forceinline__ void unpk2(float& lo, float& hi, u64 v) {
    asm("mov.b64 {%0,%1}, %2;" : "=f"(lo), "=f"(hi) : "l"(v));
}
__device__ __forceinline__ u64 pk2i(unsigned lo, unsigned hi) {
    u64 r; asm("mov.b64 %0, {%1,%2};" : "=l"(r) : "r"(lo), "r"(hi)); return r;
}
#define FMA2(d, a, b, c) asm("fma.rn.f32x2 %0, %1, %2, %3;" : "=l"(d) : "l"(a), "l"(b), "l"(c))
#define MUL2(d, a, b)    asm("mul.rn.f32x2 %0, %1, %2;"     : "=l"(d) : "l"(a), "l"(b))
#define ADD2(d, a, b)    asm("add.rn.f32x2 %0, %1, %2;"     : "=l"(d) : "l"(a), "l"(b))

// Init: zero loss accumulator; precompute per-step Adam scalars (fp64),
// one thread per step.
//   rescaled Adam: m' = m/(C1*S), v' = v/(C2*S^2), S = 1/B
//   ds = sqrt(C2/(1-B2^t)); A_t = LR*C1/((1-B1^t)*ds); E_t = (EPS/S)/ds
__global__ void wm_init_kernel() {
    const int t = threadIdx.x;
    if (t == 0) g_loss_accum = 0.0f;
    if (t >= 1 && t <= NSTEP) {
        double b1t = pow(0.9, (double)t);
        double b2t = pow(0.999, (double)t);
        double ds = sqrt(0.001 / (1.0 - b2t));
        double A  = 0.01 * 0.1 / ((1.0 - b1t) * ds);
        double E  = (1e-8 * 131072.0) / ds;
        g_ae[t] = make_float2((float)A, (float)E);
    }
}

// (128, 5): R9 showed the 6-block reg cap (85) spills the ~95-reg live state
// into the inner loop (+3.5%). 5 blocks (102 regs) is the sweet spot.
__global__ __launch_bounds__(128, 5) void wm_kernel(
    const float* __restrict__ mu_in,
    const float* __restrict__ logvar_in,
    const float* __restrict__ carrier,
    float* __restrict__ mu_out,
    float* __restrict__ logvar_out,
    int nrows)
{
    // Negated carrier in shared memory: identical for every row.
    __shared__ float4 s_cN[DIM / 4];   // 2 KB
    __shared__ float blk_loss;

    {
        const float4 cv = ((const float4*)carrier)[threadIdx.x];
        s_cN[threadIdx.x] = make_float4(-cv.x, -cv.y, -cv.z, -cv.w);
        if (threadIdx.x == 0) blk_loss = 0.0f;
    }
    __syncthreads();

    const int warp = (blockIdx.x * blockDim.x + threadIdx.x) >> 5;
    const int lane = threadIdx.x & 31;

    const float B1 = 0.9f;
    const float B2 = 0.999f;

    // Packed per-lane state: 8 f32x2 pairs each = 16 floats/lane = 512/warp
    u64 mu2[8], m2[8], v2[8];

    if (warp < nrows) {
        const float4* mrow = (const float4*)(mu_in + (size_t)warp * DIM);
        const float4* lrow = (const float4*)(logvar_in + (size_t)warp * DIM);
        float4*       lout = (float4*)(logvar_out + (size_t)warp * DIM);

#pragma unroll
        for (int i = 0; i < 4; i++) {
            float4 a = mrow[lane + 32 * i];
            mu2[2 * i]     = pk2(a.x, a.y);
            mu2[2 * i + 1] = pk2(a.z, a.w);
            lout[lane + 32 * i] = lrow[lane + 32 * i];  // log_var passthrough
            m2[2 * i] = 0ull; m2[2 * i + 1] = 0ull;
            v2[2 * i] = 0ull; v2[2 * i + 1] = 0ull;
        }

        const u64 B1_2 = pk2(B1, B1);
        const u64 B2_2 = pk2(B2, B2);
        const u64 ONE2 = pk2(1.0f, 1.0f);
        const u64 NEG1_2 = pk2(-1.0f, -1.0f);

        float loss_val = 0.0f;

        // Initial dot/norm partial accumulation (later steps fuse this into
        // the update loop so each step opens directly with the reduction).
        u64 dpa = 0ull, npa = 0ull;
#pragma unroll
        for (int i = 0; i < 4; i++) {
            float4 c4 = s_cN[lane + 32 * i];
            u64 ca = pk2(c4.x, c4.y), cb = pk2(c4.z, c4.w);
            FMA2(dpa, mu2[2 * i],     ca, dpa);
            FMA2(dpa, mu2[2 * i + 1], cb, dpa);
            FMA2(npa, mu2[2 * i],     mu2[2 * i],     npa);
            FMA2(npa, mu2[2 * i + 1], mu2[2 * i + 1], npa);
        }

#pragma unroll 1
        for (int t = 1; t <= NSTEP; ++t) {
            const float2 ae = g_ae[t];
            const float A = ae.x, E = ae.y;

            // Horizontal combine as ONE packed add: {dl,nl} + {dh,nh},
            // then packed butterfly on the {dpn, np} pair.
            float dl, dh, nl, nh;
            unpk2(dl, dh, dpa);
            unpk2(nl, nh, npa);
            u64 red = pk2(dl, nl);
            u64 redh = pk2(dh, nh);
            ADD2(red, red, redh);
#pragma unroll
            for (int off = 16; off; off >>= 1) {
                unsigned rlo = (unsigned)red, rhi = (unsigned)(red >> 32);
                unsigned slo = __shfl_xor_sync(0xffffffffu, rlo, off);
                unsigned shi = __shfl_xor_sync(0xffffffffu, rhi, off);
                u64 other = pk2i(slo, shi);
                ADD2(red, red, other);
            }
            float dpn, np;
            unpk2(dpn, np, red);    // dpn = -(mu.c), np = ||mu||^2

            const float rnorm = rsqrt_approx(np);        // 1/||mu||
            const float norm  = np * rnorm;              // ||mu||
            // COS_THETA == 1.0f in fp32; margin = norm - dot = norm + dpn.
            const float margin = norm + dpn;
            if (t == NSTEP) loss_val = fmaxf(margin, 0.0f);
            // Warp-uniform hinge mask: G &= (margin > 0). Single loop body
            // (half the I$ footprint of the duplicated-branch version).
            const u64 gmask = (margin > 0.0f) ? ~0ull : 0ull;

            const u64 rn2  = pk2(rnorm, rnorm);
            const u64 nA2  = pk2(-A, -A);
            const u64 nEE2 = pk2(-E, -E);

            dpa = 0ull; npa = 0ull;

#pragma unroll
            for (int i = 0; i < 4; i++) {
                float4 c4 = s_cN[lane + 32 * i];
                u64 cN[2] = { pk2(c4.x, c4.y), pk2(c4.z, c4.w) };
#pragma unroll
                for (int q = 0; q < 2; q++) {
                    const int p = 2 * i + q;
                    u64 G;
                    FMA2(G, rn2, mu2[p], cN[q]);         // G = mu/||mu|| - c
                    G &= gmask;                           // hinge mask (ALU)
                    FMA2(m2[p], B1_2, m2[p], G);          // m' = B1*m' + G
                    u64 gg; MUL2(gg, G, G);
                    FMA2(v2[p], B2_2, v2[p], gg);         // v' = B2*v' + G^2
                    float vlo, vhi; unpk2(vlo, vhi, v2[p]);
                    u64 s2 = pk2(sqrt_approx(vlo), sqrt_approx(vhi));
                    // nd = -(s+E) in one packed FMA2; magic seed for 1/d
                    // from bits(nd): 0x7EF477D5-bits(d) == 0xFEF477D5-bits(nd)
                    u64 nd; FMA2(nd, s2, NEG1_2, nEE2);
                    float ndlo, ndhi; unpk2(ndlo, ndhi, nd);
                    u64 y = pk2i(0xFEF477D5u - __float_as_uint(ndlo),
                                 0xFEF477D5u - __float_as_uint(ndhi));
                    // HALLEY (cubic): rel-err -e^3 in ±4e-5, sign-oscillating
                    // (no coherent bias — the R3 1-Newton failure mode).
                    //   w = -A*y0*(1 + e + e^2) = -A/(s+E)*(1 + O(e^3))
                    u64 e;  FMA2(e, nd, y, ONE2);         // e = 1 - d*y0
                    u64 e2; FMA2(e2, e, e, e);            // e + e^2
                    u64 w;  MUL2(w, nA2, y);              // -A*y0
                    FMA2(w, w, e2, w);                    // w *= (1+e+e^2)
                    FMA2(mu2[p], w, m2[p], mu2[p]);       // mu += w*m
                    // fused accumulation for next step's reduction
                    FMA2(dpa, mu2[p], cN[q], dpa);
                    FMA2(npa, mu2[p], mu2[p], npa);
                }
            }
        }

        float4* orow = (float4*)(mu_out + (size_t)warp * DIM);
#pragma unroll
        for (int i = 0; i < 4; i++) {
            float4 a;
            unpk2(a.x, a.y, mu2[2 * i]);
            unpk2(a.z, a.w, mu2[2 * i + 1]);
            orow[lane + 32 * i] = a;
        }

        if (lane == 0) atomicAdd(&blk_loss, loss_val);
    }

    __syncthreads();
    if (threadIdx.x == 0) atomicAdd(&g_loss_accum, blk_loss);
}

__global__ void wm_finalize_kernel(float* __restrict__ out_loss) {
    out_loss[0] = g_loss_accum * (1.0f / 131072.0f);
}

extern "C" void kernel_launch(void* const* d_in, const int* in_sizes, int n_in,
                              void* d_out, int out_size) {
    const float* mu      = (const float*)d_in[0];
    const float* log_var = (const float*)d_in[1];
    const float* carrier = (const float*)d_in[2];

    const int n_elem = in_sizes[0];          // 131072 * 512
    const int nrows  = n_elem / DIM;

    float* out        = (float*)d_out;
    float* mu_out     = out;
    float* logvar_out = out + n_elem;
    float* loss_out   = out + 2 * (size_t)n_elem;

    wm_init_kernel<<<1, 64>>>();

    const int threads = 128;                 // 4 warps (rows) per block
    const int blocks  = (nrows * 32 + threads - 1) / threads;
    wm_kernel<<<blocks, threads>>>(mu, log_var, carrier, mu_out, logvar_out, nrows);

    wm_finalize_kernel<<<1, 1>>>(loss_out);
}

// round 11
// speedup vs baseline: 1.0357x; 1.0006x over previous
#include <cuda_runtime.h>
#include <cstdint>

#define DIM 512
#define NSTEP 50

typedef unsigned long long u64;

__device__ float g_loss_accum;
__device__ float2 g_ae[NSTEP + 1];   // per-step {A_t, E_t}

__device__ __forceinline__ float rsqrt_approx(float x) {
    float y; asm("rsqrt.approx.f32 %0, %1;" : "=f"(y) : "f"(x)); return y;
}
__device__ __forceinline__ float sqrt_approx(float x) {
    float y; asm("sqrt.approx.f32 %0, %1;" : "=f"(y) : "f"(x)); return y;
}
__device__ __forceinline__ u64 pk2(float lo, float hi) {
    u64 r; asm("mov.b64 %0, {%1,%2};" : "=l"(r) : "f"(lo), "f"(hi)); return r;
}
__device__ __forceinline__ void unpk2(float& lo, float& hi, u64 v) {
    asm("mov.b64 {%0,%1}, %2;" : "=f"(lo), "=f"(hi) : "l"(v));
}
__device__ __forceinline__ u64 pk2i(unsigned lo, unsigned hi) {
    u64 r; asm("mov.b64 %0, {%1,%2};" : "=l"(r) : "r"(lo), "r"(hi)); return r;
}
#define FMA2(d, a, b, c) asm("fma.rn.f32x2 %0, %1, %2, %3;" : "=l"(d) : "l"(a), "l"(b), "l"(c))
#define MUL2(d, a, b)    asm("mul.rn.f32x2 %0, %1, %2;"     : "=l"(d) : "l"(a), "l"(b))
#define ADD2(d, a, b)    asm("add.rn.f32x2 %0, %1, %2;"     : "=l"(d) : "l"(a), "l"(b))

// Init: zero loss accumulator; precompute per-step Adam scalars (fp64),
// one thread per step.
//   rescaled Adam: m' = m/(C1*S), v' = v/(C2*S^2), S = 1/B
//   ds = sqrt(C2/(1-B2^t)); A_t = LR*C1/((1-B1^t)*ds); E_t = (EPS/S)/ds
__global__ void wm_init_kernel() {
    const int t = threadIdx.x;
    if (t == 0) g_loss_accum = 0.0f;
    if (t >= 1 && t <= NSTEP) {
        double b1t = pow(0.9, (double)t);
        double b2t = pow(0.999, (double)t);
        double ds = sqrt(0.001 / (1.0 - b2t));
        double A  = 0.01 * 0.1 / ((1.0 - b1t) * ds);
        double E  = (1e-8 * 131072.0) / ds;
        g_ae[t] = make_float2((float)A, (float)E);
    }
}

// TWO rows per warp: row B's packed-FMA update overlaps row A's serial
// butterfly/rsqrt phase (and vice versa) — the convoy-limited 62% fma
// utilization of the 1-row version is the target. 64-thread blocks for
// fine-grained occupancy packing at ~140 regs.
__global__ __launch_bounds__(64) void wm_kernel(
    const float* __restrict__ mu_in,
    const float* __restrict__ logvar_in,
    const float* __restrict__ carrier,
    float* __restrict__ mu_out,
    float* __restrict__ logvar_out,
    int nrows)
{
    // Negated carrier in shared memory: identical for every row.
    __shared__ float4 s_cN[DIM / 4];   // 2 KB
    __shared__ float blk_loss;

    {
        const float4 cv0 = ((const float4*)carrier)[threadIdx.x];
        const float4 cv1 = ((const float4*)carrier)[threadIdx.x + 64];
        s_cN[threadIdx.x]      = make_float4(-cv0.x, -cv0.y, -cv0.z, -cv0.w);
        s_cN[threadIdx.x + 64] = make_float4(-cv1.x, -cv1.y, -cv1.z, -cv1.w);
        if (threadIdx.x == 0) blk_loss = 0.0f;
    }
    __syncthreads();

    const int wglob = (int)((blockIdx.x * blockDim.x + threadIdx.x) >> 5);
    const int rowA = 2 * wglob;
    const int rowB = rowA + 1;
    const int lane = threadIdx.x & 31;

    const float B1 = 0.9f;
    const float B2 = 0.999f;

    // Packed per-lane state for TWO rows: 8 pairs each
    u64 muA[8], mA[8], vA[8];
    u64 muB[8], mB[8], vB[8];

    if (rowB < nrows) {
        const float4* mrowA = (const float4*)(mu_in + (size_t)rowA * DIM);
        const float4* mrowB = (const float4*)(mu_in + (size_t)rowB * DIM);
        const float4* lrowA = (const float4*)(logvar_in + (size_t)rowA * DIM);
        const float4* lrowB = (const float4*)(logvar_in + (size_t)rowB * DIM);
        float4* loutA = (float4*)(logvar_out + (size_t)rowA * DIM);
        float4* loutB = (float4*)(logvar_out + (size_t)rowB * DIM);

#pragma unroll
        for (int i = 0; i < 4; i++) {
            float4 a = mrowA[lane + 32 * i];
            float4 b = mrowB[lane + 32 * i];
            muA[2 * i]     = pk2(a.x, a.y);
            muA[2 * i + 1] = pk2(a.z, a.w);
            muB[2 * i]     = pk2(b.x, b.y);
            muB[2 * i + 1] = pk2(b.z, b.w);
            loutA[lane + 32 * i] = lrowA[lane + 32 * i];  // log_var passthrough
            loutB[lane + 32 * i] = lrowB[lane + 32 * i];
            mA[2 * i] = 0ull; mA[2 * i + 1] = 0ull;
            vA[2 * i] = 0ull; vA[2 * i + 1] = 0ull;
            mB[2 * i] = 0ull; mB[2 * i + 1] = 0ull;
            vB[2 * i] = 0ull; vB[2 * i + 1] = 0ull;
        }

        const u64 B1_2 = pk2(B1, B1);
        const u64 B2_2 = pk2(B2, B2);
        const u64 ONE2 = pk2(1.0f, 1.0f);
        const u64 NEG1_2 = pk2(-1.0f, -1.0f);

        float lossA = 0.0f, lossB = 0.0f;

        // Initial dot/norm partial accumulation for both rows.
        u64 dpaA = 0ull, npaA = 0ull, dpaB = 0ull, npaB = 0ull;
#pragma unroll
        for (int i = 0; i < 4; i++) {
            float4 c4 = s_cN[lane + 32 * i];
            u64 ca = pk2(c4.x, c4.y), cb = pk2(c4.z, c4.w);
            FMA2(dpaA, muA[2 * i],     ca, dpaA);
            FMA2(dpaA, muA[2 * i + 1], cb, dpaA);
            FMA2(npaA, muA[2 * i],     muA[2 * i],     npaA);
            FMA2(npaA, muA[2 * i + 1], muA[2 * i + 1], npaA);
            FMA2(dpaB, muB[2 * i],     ca, dpaB);
            FMA2(dpaB, muB[2 * i + 1], cb, dpaB);
            FMA2(npaB, muB[2 * i],     muB[2 * i],     npaB);
            FMA2(npaB, muB[2 * i + 1], muB[2 * i + 1], npaB);
        }

#pragma unroll 1
        for (int t = 1; t <= NSTEP; ++t) {
            const float2 ae = g_ae[t];
            const float A = ae.x, E = ae.y;

            // Two independent packed butterflies — their SHFL chains overlap.
            float dlA, dhA, nlA, nhA, dlB, dhB, nlB, nhB;
            unpk2(dlA, dhA, dpaA); unpk2(nlA, nhA, npaA);
            unpk2(dlB, dhB, dpaB); unpk2(nlB, nhB, npaB);
            u64 redA = pk2(dlA, nlA), redhA = pk2(dhA, nhA);
            u64 redB = pk2(dlB, nlB), redhB = pk2(dhB, nhB);
            ADD2(redA, redA, redhA);
            ADD2(redB, redB, redhB);
#pragma unroll
            for (int off = 16; off; off >>= 1) {
                unsigned rloA = (unsigned)redA, rhiA = (unsigned)(redA >> 32);
                unsigned rloB = (unsigned)redB, rhiB = (unsigned)(redB >> 32);
                unsigned sloA = __shfl_xor_sync(0xffffffffu, rloA, off);
                unsigned shiA = __shfl_xor_sync(0xffffffffu, rhiA, off);
                unsigned sloB = __shfl_xor_sync(0xffffffffu, rloB, off);
                unsigned shiB = __shfl_xor_sync(0xffffffffu, rhiB, off);
                u64 oA = pk2i(sloA, shiA);
                u64 oB = pk2i(sloB, shiB);
                ADD2(redA, redA, oA);
                ADD2(redB, redB, oB);
            }
            float dpnA, npA_, dpnB, npB_;
            unpk2(dpnA, npA_, redA);   // -(muA.c), ||muA||^2
            unpk2(dpnB, npB_, redB);

            const float rnormA = rsqrt_approx(npA_);
            const float rnormB = rsqrt_approx(npB_);
            const float normA = npA_ * rnormA;
            const float normB = npB_ * rnormB;
            // COS_THETA == 1.0f in fp32; margin = norm + dpn (c negated).
            const float marginA = normA + dpnA;
            const float marginB = normB + dpnB;
            if (t == NSTEP) {
                lossA = fmaxf(marginA, 0.0f);
                lossB = fmaxf(marginB, 0.0f);
            }
            const u64 gmaskA = (marginA > 0.0f) ? ~0ull : 0ull;
            const u64 gmaskB = (marginB > 0.0f) ? ~0ull : 0ull;

            const u64 rnA2 = pk2(rnormA, rnormA);
            const u64 rnB2 = pk2(rnormB, rnormB);
            const u64 nA2  = pk2(-A, -A);
            const u64 nEE2 = pk2(-E, -E);

            dpaA = 0ull; npaA = 0ull; dpaB = 0ull; npaB = 0ull;

#pragma unroll
            for (int i = 0; i < 4; i++) {
                float4 c4 = s_cN[lane + 32 * i];
                u64 cN[2] = { pk2(c4.x, c4.y), pk2(c4.z, c4.w) };
#pragma unroll
                for (int q = 0; q < 2; q++) {
                    const int p = 2 * i + q;
                    // ---- row A ----
                    {
                        u64 G;
                        FMA2(G, rnA2, muA[p], cN[q]);
                        G &= gmaskA;
                        FMA2(mA[p], B1_2, mA[p], G);
                        u64 gg; MUL2(gg, G, G);
                        FMA2(vA[p], B2_2, vA[p], gg);
                        float vlo, vhi; unpk2(vlo, vhi, vA[p]);
                        u64 s2 = pk2(sqrt_approx(vlo), sqrt_approx(vhi));
                        u64 nd; FMA2(nd, s2, NEG1_2, nEE2);   // -(s+E)
                        float ndlo, ndhi; unpk2(ndlo, ndhi, nd);
                        u64 y = pk2i(0xFEF477D5u - __float_as_uint(ndlo),
                                     0xFEF477D5u - __float_as_uint(ndhi));
                        // Halley (cubic), err ±4e-5 sign-oscillating
                        u64 e;  FMA2(e, nd, y, ONE2);
                        u64 e2; FMA2(e2, e, e, e);
                        u64 w;  MUL2(w, nA2, y);
                        FMA2(w, w, e2, w);
                        FMA2(muA[p], w, mA[p], muA[p]);
                        FMA2(dpaA, muA[p], cN[q], dpaA);
                        FMA2(npaA, muA[p], muA[p], npaA);
                    }
                    // ---- row B (independent chain, overlaps A) ----
                    {
                        u64 G;
                        FMA2(G, rnB2, muB[p], cN[q]);
                        G &= gmaskB;
                        FMA2(mB[p], B1_2, mB[p], G);
                        u64 gg; MUL2(gg, G, G);
                        FMA2(vB[p], B2_2, vB[p], gg);
                        float vlo, vhi; unpk2(vlo, vhi, vB[p]);
                        u64 s2 = pk2(sqrt_approx(vlo), sqrt_approx(vhi));
                        u64 nd; FMA2(nd, s2, NEG1_2, nEE2);
                        float ndlo, ndhi; unpk2(ndlo, ndhi, nd);
                        u64 y = pk2i(0xFEF477D5u - __float_as_uint(ndlo),
                                     0xFEF477D5u - __float_as_uint(ndhi));
                        u64 e;  FMA2(e, nd, y, ONE2);
                        u64 e2; FMA2(e2, e, e, e);
                        u64 w;  MUL2(w, nA2, y);
                        FMA2(w, w, e2, w);
                        FMA2(muB[p], w, mB[p], muB[p]);
                        FMA2(dpaB, muB[p], cN[q], dpaB);
                        FMA2(npaB, muB[p], muB[p], npaB);
                    }
                }
            }
        }

        float4* orowA = (float4*)(mu_out + (size_t)rowA * DIM);
        float4* orowB = (float4*)(mu_out + (size_t)rowB * DIM);
#pragma unroll
        for (int i = 0; i < 4; i++) {
            float4 a, b;
            unpk2(a.x, a.y, muA[2 * i]);
            unpk2(a.z, a.w, muA[2 * i + 1]);
            unpk2(b.x, b.y, muB[2 * i]);
            unpk2(b.z, b.w, muB[2 * i + 1]);
            orowA[lane + 32 * i] = a;
            orowB[lane + 32 * i] = b;
        }

        if (lane == 0) atomicAdd(&blk_loss, lossA + lossB);
    }

    __syncthreads();
    if (threadIdx.x == 0) atomicAdd(&g_loss_accum, blk_loss);
}

__global__ void wm_finalize_kernel(float* __restrict__ out_loss) {
    out_loss[0] = g_loss_accum * (1.0f / 131072.0f);
}

extern "C" void kernel_launch(void* const* d_in, const int* in_sizes, int n_in,
                              void* d_out, int out_size) {
    const float* mu      = (const float*)d_in[0];
    const float* log_var = (const float*)d_in[1];
    const float* carrier = (const float*)d_in[2];

    const int n_elem = in_sizes[0];          // 131072 * 512
    const int nrows  = n_elem / DIM;

    float* out        = (float*)d_out;
    float* mu_out     = out;
    float* logvar_out = out + n_elem;
    float* loss_out   = out + 2 * (size_t)n_elem;

    wm_init_kernel<<<1, 64>>>();

    const int threads = 64;                  // 2 warps/block, 2 rows/warp
    const int nwarps  = nrows / 2;           // 131072 rows -> 65536 warps
    const int blocks  = (nwarps * 32 + threads - 1) / threads;
    wm_kernel<<<blocks, threads>>>(mu, log_var, carrier, mu_out, logvar_out, nrows);

    wm_finalize_kernel<<<1, 1>>>(loss_out);
}